// round 6
// baseline (speedup 1.0000x reference)
#include <cuda_runtime.h>

#define NU 100000
#define NE 100000
#define NN 200000
#define C  64
#define N_HOPS 3
#define NT (NE + NN + NU)            // combined destination space
#define MAXREC 4000000               // E + E2 + NNZ
#define SCAN_BLK 1024
#define NB ((NT + SCAN_BLK - 1) / SCAN_BLK)

// -------- persistent scratch (static device globals) --------
__device__ __align__(16) float g_all0[(size_t)NN * C];   // ping
__device__ __align__(16) float g_all1[(size_t)NN * C];   // pong
__device__ __align__(16) float g_w[31 * C];              // combined weight tables
__device__ __align__(16) float g_f[NE];                  // per-hop ||sum||/cnt
__device__ int  g_cnt[NT];
__device__ int  g_rowptr[NT + 1];
__device__ int  g_cursor[NT];
__device__ int  g_blocksums[NB];
__device__ __align__(16) int2 g_rec[MAXREC];

// ---------------------------------------------------------------------------
__global__ void init_kernel(const float* __restrict__ user_emb,
                            const float* __restrict__ entity_emb,
                            const float* __restrict__ w,
                            const float* __restrict__ w2,
                            float* __restrict__ out) {
    const size_t nn4   = (size_t)NN * C / 4;
    const size_t nu4   = (size_t)NU * C / 4;
    const size_t cnt_n = NT;
    const size_t total = nn4 + cnt_n + 31 * C;
    float4*       all4 = (float4*)g_all0;
    const float4* ue4  = (const float4*)user_emb;
    const float4* ee4  = (const float4*)entity_emb;
    float4*       out4 = (float4*)out;
    for (size_t i = (size_t)blockIdx.x * blockDim.x + threadIdx.x;
         i < total; i += (size_t)gridDim.x * blockDim.x) {
        if (i < nn4) {
            float4 v;
            if (i < nu4) { v = ue4[i]; out4[i] = v; }      // user_res init
            else         { v = ee4[i - nu4]; }
            all4[i] = v;
            out4[nn4 + i] = v;                             // node_res init
        } else if (i < nn4 + cnt_n) {
            g_cnt[i - nn4] = 0;
        } else {
            size_t j = i - nn4 - cnt_n;
            g_w[j] = (j < 15 * C) ? w[j] : w2[j - 15 * C];
        }
    }
}

// ---------------------------------------------------------------------------
// CSR build (one-time)
// dest space: [0,NE): entity edges | [NE,NE+NN): node edges | [NE+NN,NT): im
// ---------------------------------------------------------------------------
__global__ void hist_kernel(const int* __restrict__ ei,
                            const int* __restrict__ e2i,
                            const int* __restrict__ im_row,
                            int E, int E2, int NNZ) {
    int i = blockIdx.x * blockDim.x + threadIdx.x;
    int total = E + E2 + NNZ;
    if (i >= total) return;
    int d;
    if (i < E)           d = ei[i];
    else if (i < E + E2) d = NE + e2i[i - E];
    else                 d = NE + NN + im_row[i - E - E2];
    atomicAdd(g_cnt + d, 1);
}

__global__ void scan1_kernel() {
    __shared__ int s[256];
    int tid  = threadIdx.x;
    int base = blockIdx.x * SCAN_BLK + tid * 4;
    int v[4], t = 0;
    #pragma unroll
    for (int k = 0; k < 4; k++) {
        v[k] = (base + k < NT) ? g_cnt[base + k] : 0;
        t += v[k];
    }
    s[tid] = t;
    __syncthreads();
    #pragma unroll
    for (int off = 1; off < 256; off <<= 1) {
        int x = (tid >= off) ? s[tid - off] : 0;
        __syncthreads();
        s[tid] += x;
        __syncthreads();
    }
    int excl = s[tid] - t;
    if (tid == 255) g_blocksums[blockIdx.x] = s[255];
    int run = excl;
    #pragma unroll
    for (int k = 0; k < 4; k++) {
        if (base + k < NT) g_rowptr[base + k] = run;
        run += v[k];
    }
}

// parallel scan over block sums (NB <= 512)
__global__ void scan2_kernel() {
    __shared__ int s[512];
    int tid = threadIdx.x;
    int v = (tid < NB) ? g_blocksums[tid] : 0;
    s[tid] = v;
    __syncthreads();
    #pragma unroll
    for (int off = 1; off < 512; off <<= 1) {
        int x = (tid >= off) ? s[tid - off] : 0;
        __syncthreads();
        s[tid] += x;
        __syncthreads();
    }
    if (tid < NB) g_blocksums[tid] = s[tid] - v;   // exclusive
}

__global__ void scan3_kernel(int total_rec) {
    int i = blockIdx.x * blockDim.x + threadIdx.x;
    if (i < NT) {
        int v = g_rowptr[i] + g_blocksums[i / SCAN_BLK];
        g_rowptr[i] = v;
        g_cursor[i] = v;
    }
    if (i == 0) g_rowptr[NT] = total_rec;
}

__global__ void fill_kernel(const int* __restrict__ ei,  const int* __restrict__ ety,
                            const int* __restrict__ e2i, const int* __restrict__ e2ty,
                            const int* __restrict__ im_row, const int* __restrict__ im_col,
                            const float* __restrict__ im_val,
                            int E, int E2, int NNZ) {
    int i = blockIdx.x * blockDim.x + threadIdx.x;
    int total = E + E2 + NNZ;
    if (i >= total) return;
    int d; int2 rec;
    if (i < E) {
        d     = ei[i];
        rec.x = NU + ei[E + i];            // src row (entity half of g_all)
        rec.y = ety[i] - 1;                // weight row 0..14
    } else if (i < E + E2) {
        int e2 = i - E;
        d     = NE + e2i[e2];
        rec.x = e2i[E2 + e2];              // src row (node space)
        rec.y = 15 + e2ty[e2];             // weight row 15..30
    } else {
        int j = i - E - E2;
        d     = NE + NN + im_row[j];
        rec.x = im_col[j];                 // entity col
        rec.y = __float_as_int(im_val[j]); // raw im value
    }
    int pos = atomicAdd(g_cursor + d, 1);
    g_rec[pos] = rec;
}

// ---------------------------------------------------------------------------
// per-hop gathers: 16-lane group per destination row, float4 per lane
// ---------------------------------------------------------------------------
__device__ __forceinline__ float grp_sum16(float s) {
    #pragma unroll
    for (int o = 8; o; o >>= 1) s += __shfl_xor_sync(0xffffffffu, s, o);
    return s;
}

__global__ void __launch_bounds__(256) gather_kernel(
    int flip, float* __restrict__ node_res, float* __restrict__ ent_out)
{
    const float* prev = flip ? g_all1 : g_all0;
    float*       next = flip ? g_all0 : g_all1;

    int gidx = (blockIdx.x * blockDim.x + threadIdx.x) >> 4;
    int lane = threadIdx.x & 15;
    if (gidx >= NE + NN) return;
    int start = g_rowptr[gidx], end = g_rowptr[gidx + 1];

    float4 acc = make_float4(0.f, 0.f, 0.f, 0.f);
    int e = start;
    for (; e + 3 < end; e += 4) {
        int2 r0 = __ldg(g_rec + e);
        int2 r1 = __ldg(g_rec + e + 1);
        int2 r2 = __ldg(g_rec + e + 2);
        int2 r3 = __ldg(g_rec + e + 3);
        float4 s0 = *((const float4*)(prev + (size_t)r0.x * C) + lane);
        float4 s1 = *((const float4*)(prev + (size_t)r1.x * C) + lane);
        float4 s2 = *((const float4*)(prev + (size_t)r2.x * C) + lane);
        float4 s3 = *((const float4*)(prev + (size_t)r3.x * C) + lane);
        float4 w0 = *((const float4*)(g_w + r0.y * C) + lane);
        float4 w1 = *((const float4*)(g_w + r1.y * C) + lane);
        float4 w2 = *((const float4*)(g_w + r2.y * C) + lane);
        float4 w3 = *((const float4*)(g_w + r3.y * C) + lane);
        acc.x += s0.x * w0.x + s1.x * w1.x + s2.x * w2.x + s3.x * w3.x;
        acc.y += s0.y * w0.y + s1.y * w1.y + s2.y * w2.y + s3.y * w3.y;
        acc.z += s0.z * w0.z + s1.z * w1.z + s2.z * w2.z + s3.z * w3.z;
        acc.w += s0.w * w0.w + s1.w * w1.w + s2.w * w2.w + s3.w * w3.w;
    }
    for (; e < end; e++) {
        int2 r0 = __ldg(g_rec + e);
        float4 s0 = *((const float4*)(prev + (size_t)r0.x * C) + lane);
        float4 w0 = *((const float4*)(g_w + r0.y * C) + lane);
        acc.x += s0.x * w0.x; acc.y += s0.y * w0.y;
        acc.z += s0.z * w0.z; acc.w += s0.w * w0.w;
    }

    float ss = grp_sum16(acc.x * acc.x + acc.y * acc.y + acc.z * acc.z + acc.w * acc.w);
    float n  = sqrtf(ss);
    float inv = 1.0f / fmaxf(n, 1e-12f);
    float4 o = make_float4(acc.x * inv, acc.y * inv, acc.z * inv, acc.w * inv);

    if (gidx < NE) {
        *((float4*)(next + (size_t)(NU + gidx) * C) + lane) = o;
        if (lane == 0) g_f[gidx] = n / fmaxf((float)(end - start), 1.0f);
        if (ent_out) *((float4*)(ent_out + (size_t)gidx * C) + lane) = o;
    } else {
        int r = gidx - NE;
        if (r < NU) *((float4*)(next + (size_t)r * C) + lane) = o;
        float4* rp = (float4*)(node_res + (size_t)r * C) + lane;
        float4 a = *rp;
        a.x += o.x; a.y += o.y; a.z += o.z; a.w += o.w;
        *rp = a;
    }
}

__global__ void __launch_bounds__(256) im_gather_kernel(
    int flip, float* __restrict__ user_res)
{
    const float* next = flip ? g_all0 : g_all1;   // buffer just written

    int gidx = (blockIdx.x * blockDim.x + threadIdx.x) >> 4;
    int lane = threadIdx.x & 15;
    if (gidx >= NU) return;
    int row = NE + NN + gidx;
    int start = g_rowptr[row], end = g_rowptr[row + 1];

    float4 acc = make_float4(0.f, 0.f, 0.f, 0.f);
    int e = start;
    for (; e + 3 < end; e += 4) {
        int2 r0 = __ldg(g_rec + e);
        int2 r1 = __ldg(g_rec + e + 1);
        int2 r2 = __ldg(g_rec + e + 2);
        int2 r3 = __ldg(g_rec + e + 3);
        float c0 = __int_as_float(r0.y) * __ldg(g_f + r0.x);
        float c1 = __int_as_float(r1.y) * __ldg(g_f + r1.x);
        float c2 = __int_as_float(r2.y) * __ldg(g_f + r2.x);
        float c3 = __int_as_float(r3.y) * __ldg(g_f + r3.x);
        float4 s0 = *((const float4*)(next + (size_t)(NU + r0.x) * C) + lane);
        float4 s1 = *((const float4*)(next + (size_t)(NU + r1.x) * C) + lane);
        float4 s2 = *((const float4*)(next + (size_t)(NU + r2.x) * C) + lane);
        float4 s3 = *((const float4*)(next + (size_t)(NU + r3.x) * C) + lane);
        acc.x += s0.x * c0 + s1.x * c1 + s2.x * c2 + s3.x * c3;
        acc.y += s0.y * c0 + s1.y * c1 + s2.y * c2 + s3.y * c3;
        acc.z += s0.z * c0 + s1.z * c1 + s2.z * c2 + s3.z * c3;
        acc.w += s0.w * c0 + s1.w * c1 + s2.w * c2 + s3.w * c3;
    }
    for (; e < end; e++) {
        int2 r0 = __ldg(g_rec + e);
        float c0 = __int_as_float(r0.y) * __ldg(g_f + r0.x);
        float4 s0 = *((const float4*)(next + (size_t)(NU + r0.x) * C) + lane);
        acc.x += s0.x * c0; acc.y += s0.y * c0;
        acc.z += s0.z * c0; acc.w += s0.w * c0;
    }

    float ss = grp_sum16(acc.x * acc.x + acc.y * acc.y + acc.z * acc.z + acc.w * acc.w);
    float inv = 1.0f / fmaxf(sqrtf(ss), 1e-12f);
    float4* rp = (float4*)(user_res + (size_t)gidx * C) + lane;
    float4 a = *rp;
    a.x += acc.x * inv; a.y += acc.y * inv;
    a.z += acc.z * inv; a.w += acc.w * inv;
    *rp = a;
}

// ---------------------------------------------------------------------------
extern "C" void kernel_launch(void* const* d_in, const int* in_sizes, int n_in,
                              void* d_out, int out_size) {
    const float* user_emb     = (const float*)d_in[0];
    const float* entity_emb   = (const float*)d_in[1];
    const float* weight       = (const float*)d_in[2];
    const float* extra_weight = (const float*)d_in[3];
    const float* im_val       = (const float*)d_in[4];
    const int*   edge_index   = (const int*)d_in[5];
    const int*   edge_type    = (const int*)d_in[6];
    const int*   extra_eidx   = (const int*)d_in[7];
    const int*   extra_etype  = (const int*)d_in[8];
    const int*   im_row       = (const int*)d_in[9];
    const int*   im_col       = (const int*)d_in[10];

    const int E   = in_sizes[6];
    const int E2  = in_sizes[8];
    const int NNZ = in_sizes[4];
    const int total_rec = E + E2 + NNZ;

    float* out      = (float*)d_out;
    float* user_res = out;                      // [NU, C]
    float* ent_out  = out + (size_t)NU * C;     // [NE, C]
    float* node_res = out + (size_t)NN * C;     // [NN, C]

    init_kernel<<<2048, 256>>>(user_emb, entity_emb, weight, extra_weight, out);
    hist_kernel<<<(total_rec + 255) / 256, 256>>>(edge_index, extra_eidx, im_row, E, E2, NNZ);
    scan1_kernel<<<NB, 256>>>();
    scan2_kernel<<<1, 512>>>();
    scan3_kernel<<<(NT + 255) / 256, 256>>>(total_rec);
    fill_kernel<<<(total_rec + 255) / 256, 256>>>(edge_index, edge_type,
                                                  extra_eidx, extra_etype,
                                                  im_row, im_col, im_val, E, E2, NNZ);

    const int gather_blocks = ((NE + NN) * 16 + 255) / 256;
    const int im_blocks     = (NU * 16 + 255) / 256;

    for (int hop = 0; hop < N_HOPS; hop++) {
        int flip = hop & 1;
        gather_kernel<<<gather_blocks, 256>>>(flip, node_res,
                                              hop == N_HOPS - 1 ? ent_out : nullptr);
        im_gather_kernel<<<im_blocks, 256>>>(flip, user_res);
    }
}

// round 7
// speedup vs baseline: 1.0609x; 1.0609x over previous
#include <cuda_runtime.h>
#include <cuda_fp16.h>

#define NU 100000
#define NE 100000
#define NN 200000
#define C  64
#define N_HOPS 3
#define NT (NE + NN + NU)            // combined destination space
#define MAXREC 4000000               // E + E2 + NNZ
#define SCAN_BLK 1024
#define NB ((NT + SCAN_BLK - 1) / SCAN_BLK)

// -------- persistent scratch (static device globals) --------
__device__ __align__(16) __half g_all0[(size_t)NN * C];  // ping (fp16)
__device__ __align__(16) __half g_all1[(size_t)NN * C];  // pong (fp16)
__device__ __align__(16) float  g_w[31 * C];             // combined weight tables (fp32)
__device__ __align__(16) float  g_f[NE];                 // per-hop ||sum||/cnt
__device__ int  g_cnt[NT];
__device__ int  g_rowptr[NT + 1];
__device__ int  g_cursor[NT];
__device__ int  g_blocksums[NB];
__device__ __align__(16) int2 g_rec[MAXREC];

// ---------------------------------------------------------------------------
// init: g_all0 = fp16([user_emb ; entity_emb]); out.user_res/node_res init;
//       zero g_cnt; stage combined weight table
// ---------------------------------------------------------------------------
__global__ void init_kernel(const float* __restrict__ user_emb,
                            const float* __restrict__ entity_emb,
                            const float* __restrict__ w,
                            const float* __restrict__ w2,
                            float* __restrict__ out) {
    const size_t nn4   = (size_t)NN * C / 4;
    const size_t nu4   = (size_t)NU * C / 4;
    const size_t cnt_n = NT;
    const size_t total = nn4 + cnt_n + 31 * C;
    uint2*        all2 = (uint2*)g_all0;            // 4 halves per uint2
    const float4* ue4  = (const float4*)user_emb;
    const float4* ee4  = (const float4*)entity_emb;
    float4*       out4 = (float4*)out;
    for (size_t i = (size_t)blockIdx.x * blockDim.x + threadIdx.x;
         i < total; i += (size_t)gridDim.x * blockDim.x) {
        if (i < nn4) {
            float4 v;
            if (i < nu4) { v = ue4[i]; out4[i] = v; }      // user_res init
            else         { v = ee4[i - nu4]; }
            uint2 h;
            *(__half2*)&h.x = __floats2half2_rn(v.x, v.y);
            *(__half2*)&h.y = __floats2half2_rn(v.z, v.w);
            all2[i] = h;
            out4[nn4 + i] = v;                             // node_res init
        } else if (i < nn4 + cnt_n) {
            g_cnt[i - nn4] = 0;
        } else {
            size_t j = i - nn4 - cnt_n;
            g_w[j] = (j < 15 * C) ? w[j] : w2[j - 15 * C];
        }
    }
}

// ---------------------------------------------------------------------------
// CSR build (one-time)
// dest space: [0,NE): entity edges | [NE,NE+NN): node edges | [NE+NN,NT): im
// ---------------------------------------------------------------------------
__global__ void hist_kernel(const int* __restrict__ ei,
                            const int* __restrict__ e2i,
                            const int* __restrict__ im_row,
                            int E, int E2, int NNZ) {
    int i = blockIdx.x * blockDim.x + threadIdx.x;
    int total = E + E2 + NNZ;
    if (i >= total) return;
    int d;
    if (i < E)           d = ei[i];
    else if (i < E + E2) d = NE + e2i[i - E];
    else                 d = NE + NN + im_row[i - E - E2];
    atomicAdd(g_cnt + d, 1);
}

__global__ void scan1_kernel() {
    __shared__ int s[256];
    int tid  = threadIdx.x;
    int base = blockIdx.x * SCAN_BLK + tid * 4;
    int v[4], t = 0;
    #pragma unroll
    for (int k = 0; k < 4; k++) {
        v[k] = (base + k < NT) ? g_cnt[base + k] : 0;
        t += v[k];
    }
    s[tid] = t;
    __syncthreads();
    #pragma unroll
    for (int off = 1; off < 256; off <<= 1) {
        int x = (tid >= off) ? s[tid - off] : 0;
        __syncthreads();
        s[tid] += x;
        __syncthreads();
    }
    int excl = s[tid] - t;
    if (tid == 255) g_blocksums[blockIdx.x] = s[255];
    int run = excl;
    #pragma unroll
    for (int k = 0; k < 4; k++) {
        if (base + k < NT) g_rowptr[base + k] = run;
        run += v[k];
    }
}

// parallel scan over block sums (NB <= 512)
__global__ void scan2_kernel() {
    __shared__ int s[512];
    int tid = threadIdx.x;
    int v = (tid < NB) ? g_blocksums[tid] : 0;
    s[tid] = v;
    __syncthreads();
    #pragma unroll
    for (int off = 1; off < 512; off <<= 1) {
        int x = (tid >= off) ? s[tid - off] : 0;
        __syncthreads();
        s[tid] += x;
        __syncthreads();
    }
    if (tid < NB) g_blocksums[tid] = s[tid] - v;   // exclusive
}

__global__ void scan3_kernel(int total_rec) {
    int i = blockIdx.x * blockDim.x + threadIdx.x;
    if (i < NT) {
        int v = g_rowptr[i] + g_blocksums[i / SCAN_BLK];
        g_rowptr[i] = v;
        g_cursor[i] = v;
    }
    if (i == 0) g_rowptr[NT] = total_rec;
}

__global__ void fill_kernel(const int* __restrict__ ei,  const int* __restrict__ ety,
                            const int* __restrict__ e2i, const int* __restrict__ e2ty,
                            const int* __restrict__ im_row, const int* __restrict__ im_col,
                            const float* __restrict__ im_val,
                            int E, int E2, int NNZ) {
    int i = blockIdx.x * blockDim.x + threadIdx.x;
    int total = E + E2 + NNZ;
    if (i >= total) return;
    int d; int2 rec;
    if (i < E) {
        d     = ei[i];
        rec.x = NU + ei[E + i];            // src row (entity half of g_all)
        rec.y = ety[i] - 1;                // weight row 0..14
    } else if (i < E + E2) {
        int e2 = i - E;
        d     = NE + e2i[e2];
        rec.x = e2i[E2 + e2];              // src row (node space)
        rec.y = 15 + e2ty[e2];             // weight row 15..30
    } else {
        int j = i - E - E2;
        d     = NE + NN + im_row[j];
        rec.x = im_col[j];                 // entity col
        rec.y = __float_as_int(im_val[j]); // raw im value
    }
    int pos = atomicAdd(g_cursor + d, 1);
    g_rec[pos] = rec;
}

// ---------------------------------------------------------------------------
// per-hop gathers: 16-lane group per destination row.
// fp16 src (uint2 = 4 halves per lane), fp32 weights & accumulation.
// ---------------------------------------------------------------------------
__device__ __forceinline__ float grp_sum16(float s) {
    #pragma unroll
    for (int o = 8; o; o >>= 1) s += __shfl_xor_sync(0xffffffffu, s, o);
    return s;
}

__device__ __forceinline__ float4 h4_to_f4(uint2 h) {
    float2 a = __half22float2(*(__half2*)&h.x);
    float2 b = __half22float2(*(__half2*)&h.y);
    return make_float4(a.x, a.y, b.x, b.y);
}

__global__ void __launch_bounds__(256) gather_kernel(
    int flip, float* __restrict__ node_res, float* __restrict__ ent_out)
{
    const __half* prev = flip ? g_all1 : g_all0;
    __half*       next = flip ? g_all0 : g_all1;

    int gidx = (blockIdx.x * blockDim.x + threadIdx.x) >> 4;
    int lane = threadIdx.x & 15;
    if (gidx >= NE + NN) return;
    int start = g_rowptr[gidx], end = g_rowptr[gidx + 1];

    float4 acc = make_float4(0.f, 0.f, 0.f, 0.f);
    int e = start;
    for (; e + 1 < end; e += 2) {
        int2 r0 = __ldg(g_rec + e);
        int2 r1 = __ldg(g_rec + e + 1);
        uint2 h0 = *((const uint2*)(prev + (size_t)r0.x * C) + lane);
        uint2 h1 = *((const uint2*)(prev + (size_t)r1.x * C) + lane);
        float4 w0 = *((const float4*)(g_w + r0.y * C) + lane);
        float4 w1 = *((const float4*)(g_w + r1.y * C) + lane);
        float4 s0 = h4_to_f4(h0);
        float4 s1 = h4_to_f4(h1);
        acc.x += s0.x * w0.x + s1.x * w1.x;
        acc.y += s0.y * w0.y + s1.y * w1.y;
        acc.z += s0.z * w0.z + s1.z * w1.z;
        acc.w += s0.w * w0.w + s1.w * w1.w;
    }
    if (e < end) {
        int2 r0 = __ldg(g_rec + e);
        uint2 h0 = *((const uint2*)(prev + (size_t)r0.x * C) + lane);
        float4 w0 = *((const float4*)(g_w + r0.y * C) + lane);
        float4 s0 = h4_to_f4(h0);
        acc.x += s0.x * w0.x; acc.y += s0.y * w0.y;
        acc.z += s0.z * w0.z; acc.w += s0.w * w0.w;
    }

    float ss = grp_sum16(acc.x * acc.x + acc.y * acc.y + acc.z * acc.z + acc.w * acc.w);
    float n  = sqrtf(ss);
    float inv = 1.0f / fmaxf(n, 1e-12f);
    float4 o = make_float4(acc.x * inv, acc.y * inv, acc.z * inv, acc.w * inv);
    uint2 oh;
    *(__half2*)&oh.x = __floats2half2_rn(o.x, o.y);
    *(__half2*)&oh.y = __floats2half2_rn(o.z, o.w);

    if (gidx < NE) {
        *((uint2*)(next + (size_t)(NU + gidx) * C) + lane) = oh;
        if (lane == 0) g_f[gidx] = n / fmaxf((float)(end - start), 1.0f);
        if (ent_out) *((float4*)(ent_out + (size_t)gidx * C) + lane) = o;
    } else {
        int r = gidx - NE;
        if (r < NU) *((uint2*)(next + (size_t)r * C) + lane) = oh;
        float4* rp = (float4*)(node_res + (size_t)r * C) + lane;
        float4 a = *rp;
        a.x += o.x; a.y += o.y; a.z += o.z; a.w += o.w;
        *rp = a;
    }
}

__global__ void __launch_bounds__(256) im_gather_kernel(
    int flip, float* __restrict__ user_res)
{
    const __half* next = flip ? g_all0 : g_all1;   // buffer just written

    int gidx = (blockIdx.x * blockDim.x + threadIdx.x) >> 4;
    int lane = threadIdx.x & 15;
    if (gidx >= NU) return;
    int row = NE + NN + gidx;
    int start = g_rowptr[row], end = g_rowptr[row + 1];

    float4 acc = make_float4(0.f, 0.f, 0.f, 0.f);
    int e = start;
    for (; e + 1 < end; e += 2) {
        int2 r0 = __ldg(g_rec + e);
        int2 r1 = __ldg(g_rec + e + 1);
        float c0 = __int_as_float(r0.y) * __ldg(g_f + r0.x);
        float c1 = __int_as_float(r1.y) * __ldg(g_f + r1.x);
        uint2 h0 = *((const uint2*)(next + (size_t)(NU + r0.x) * C) + lane);
        uint2 h1 = *((const uint2*)(next + (size_t)(NU + r1.x) * C) + lane);
        float4 s0 = h4_to_f4(h0);
        float4 s1 = h4_to_f4(h1);
        acc.x += s0.x * c0 + s1.x * c1;
        acc.y += s0.y * c0 + s1.y * c1;
        acc.z += s0.z * c0 + s1.z * c1;
        acc.w += s0.w * c0 + s1.w * c1;
    }
    if (e < end) {
        int2 r0 = __ldg(g_rec + e);
        float c0 = __int_as_float(r0.y) * __ldg(g_f + r0.x);
        uint2 h0 = *((const uint2*)(next + (size_t)(NU + r0.x) * C) + lane);
        float4 s0 = h4_to_f4(h0);
        acc.x += s0.x * c0; acc.y += s0.y * c0;
        acc.z += s0.z * c0; acc.w += s0.w * c0;
    }

    float ss = grp_sum16(acc.x * acc.x + acc.y * acc.y + acc.z * acc.z + acc.w * acc.w);
    float inv = 1.0f / fmaxf(sqrtf(ss), 1e-12f);
    float4* rp = (float4*)(user_res + (size_t)gidx * C) + lane;
    float4 a = *rp;
    a.x += acc.x * inv; a.y += acc.y * inv;
    a.z += acc.z * inv; a.w += acc.w * inv;
    *rp = a;
}

// ---------------------------------------------------------------------------
extern "C" void kernel_launch(void* const* d_in, const int* in_sizes, int n_in,
                              void* d_out, int out_size) {
    const float* user_emb     = (const float*)d_in[0];
    const float* entity_emb   = (const float*)d_in[1];
    const float* weight       = (const float*)d_in[2];
    const float* extra_weight = (const float*)d_in[3];
    const float* im_val       = (const float*)d_in[4];
    const int*   edge_index   = (const int*)d_in[5];
    const int*   edge_type    = (const int*)d_in[6];
    const int*   extra_eidx   = (const int*)d_in[7];
    const int*   extra_etype  = (const int*)d_in[8];
    const int*   im_row       = (const int*)d_in[9];
    const int*   im_col       = (const int*)d_in[10];

    const int E   = in_sizes[6];
    const int E2  = in_sizes[8];
    const int NNZ = in_sizes[4];
    const int total_rec = E + E2 + NNZ;

    float* out      = (float*)d_out;
    float* user_res = out;                      // [NU, C]
    float* ent_out  = out + (size_t)NU * C;     // [NE, C]
    float* node_res = out + (size_t)NN * C;     // [NN, C]

    init_kernel<<<2048, 256>>>(user_emb, entity_emb, weight, extra_weight, out);
    hist_kernel<<<(total_rec + 255) / 256, 256>>>(edge_index, extra_eidx, im_row, E, E2, NNZ);
    scan1_kernel<<<NB, 256>>>();
    scan2_kernel<<<1, 512>>>();
    scan3_kernel<<<(NT + 255) / 256, 256>>>(total_rec);
    fill_kernel<<<(total_rec + 255) / 256, 256>>>(edge_index, edge_type,
                                                  extra_eidx, extra_etype,
                                                  im_row, im_col, im_val, E, E2, NNZ);

    const int gather_blocks = ((NE + NN) * 16 + 255) / 256;
    const int im_blocks     = (NU * 16 + 255) / 256;

    for (int hop = 0; hop < N_HOPS; hop++) {
        int flip = hop & 1;
        gather_kernel<<<gather_blocks, 256>>>(flip, node_res,
                                              hop == N_HOPS - 1 ? ent_out : nullptr);
        im_gather_kernel<<<im_blocks, 256>>>(flip, user_res);
    }
}

// round 8
// speedup vs baseline: 1.2384x; 1.1673x over previous
#include <cuda_runtime.h>
#include <cuda_fp16.h>

#define NU 100000
#define NE 100000
#define NN 200000
#define C  64
#define N_HOPS 3
#define NT (NE + NN + NU)            // combined destination space
#define MAXREC 4000000               // E + E2 + NNZ
#define SCAN_BLK 1024
#define NB ((NT + SCAN_BLK - 1) / SCAN_BLK)

// -------- persistent scratch (static device globals) --------
__device__ __align__(16) __half g_all0[(size_t)NN * C];  // ping (fp16)
__device__ __align__(16) __half g_all1[(size_t)NN * C];  // pong (fp16)
__device__ __align__(16) float  g_w[31 * C];             // combined weight tables (fp32)
__device__ __align__(16) float  g_f[NE];                 // per-hop ||sum||/cnt
__device__ int  g_cnt[NT];
__device__ int  g_rowptr[NT + 1];
__device__ int  g_cursor[NT];
__device__ int  g_blocksums[NB];
__device__ __align__(16) int2 g_rec[MAXREC];

// ---------------------------------------------------------------------------
__global__ void init_kernel(const float* __restrict__ user_emb,
                            const float* __restrict__ entity_emb,
                            const float* __restrict__ w,
                            const float* __restrict__ w2,
                            float* __restrict__ out) {
    const size_t nn4   = (size_t)NN * C / 4;
    const size_t nu4   = (size_t)NU * C / 4;
    const size_t cnt_n = NT;
    const size_t total = nn4 + cnt_n + 31 * C;
    uint2*        all2 = (uint2*)g_all0;            // 4 halves per uint2
    const float4* ue4  = (const float4*)user_emb;
    const float4* ee4  = (const float4*)entity_emb;
    float4*       out4 = (float4*)out;
    for (size_t i = (size_t)blockIdx.x * blockDim.x + threadIdx.x;
         i < total; i += (size_t)gridDim.x * blockDim.x) {
        if (i < nn4) {
            float4 v;
            if (i < nu4) { v = ue4[i]; out4[i] = v; }      // user_res init
            else         { v = ee4[i - nu4]; }
            uint2 h;
            *(__half2*)&h.x = __floats2half2_rn(v.x, v.y);
            *(__half2*)&h.y = __floats2half2_rn(v.z, v.w);
            all2[i] = h;
            out4[nn4 + i] = v;                             // node_res init
        } else if (i < nn4 + cnt_n) {
            g_cnt[i - nn4] = 0;
        } else {
            size_t j = i - nn4 - cnt_n;
            g_w[j] = (j < 15 * C) ? w[j] : w2[j - 15 * C];
        }
    }
}

// ---------------------------------------------------------------------------
// CSR build (one-time)
// dest space: [0,NE): entity edges | [NE,NE+NN): node edges | [NE+NN,NT): im
// ---------------------------------------------------------------------------
__global__ void hist_kernel(const int* __restrict__ ei,
                            const int* __restrict__ e2i,
                            const int* __restrict__ im_row,
                            int E, int E2, int NNZ) {
    int i = blockIdx.x * blockDim.x + threadIdx.x;
    int total = E + E2 + NNZ;
    if (i >= total) return;
    int d;
    if (i < E)           d = ei[i];
    else if (i < E + E2) d = NE + e2i[i - E];
    else                 d = NE + NN + im_row[i - E - E2];
    atomicAdd(g_cnt + d, 1);
}

__global__ void scan1_kernel() {
    __shared__ int s[256];
    int tid  = threadIdx.x;
    int base = blockIdx.x * SCAN_BLK + tid * 4;
    int v[4], t = 0;
    #pragma unroll
    for (int k = 0; k < 4; k++) {
        v[k] = (base + k < NT) ? g_cnt[base + k] : 0;
        t += v[k];
    }
    s[tid] = t;
    __syncthreads();
    #pragma unroll
    for (int off = 1; off < 256; off <<= 1) {
        int x = (tid >= off) ? s[tid - off] : 0;
        __syncthreads();
        s[tid] += x;
        __syncthreads();
    }
    int excl = s[tid] - t;
    if (tid == 255) g_blocksums[blockIdx.x] = s[255];
    int run = excl;
    #pragma unroll
    for (int k = 0; k < 4; k++) {
        if (base + k < NT) g_rowptr[base + k] = run;
        run += v[k];
    }
}

// parallel scan over block sums (NB <= 512)
__global__ void scan2_kernel() {
    __shared__ int s[512];
    int tid = threadIdx.x;
    int v = (tid < NB) ? g_blocksums[tid] : 0;
    s[tid] = v;
    __syncthreads();
    #pragma unroll
    for (int off = 1; off < 512; off <<= 1) {
        int x = (tid >= off) ? s[tid - off] : 0;
        __syncthreads();
        s[tid] += x;
        __syncthreads();
    }
    if (tid < NB) g_blocksums[tid] = s[tid] - v;   // exclusive
}

__global__ void scan3_kernel(int total_rec) {
    int i = blockIdx.x * blockDim.x + threadIdx.x;
    if (i < NT) {
        int v = g_rowptr[i] + g_blocksums[i / SCAN_BLK];
        g_rowptr[i] = v;
        g_cursor[i] = v;
    }
    if (i == 0) g_rowptr[NT] = total_rec;
}

__global__ void fill_kernel(const int* __restrict__ ei,  const int* __restrict__ ety,
                            const int* __restrict__ e2i, const int* __restrict__ e2ty,
                            const int* __restrict__ im_row, const int* __restrict__ im_col,
                            const float* __restrict__ im_val,
                            int E, int E2, int NNZ) {
    int i = blockIdx.x * blockDim.x + threadIdx.x;
    int total = E + E2 + NNZ;
    if (i >= total) return;
    int d; int2 rec;
    if (i < E) {
        d     = ei[i];
        rec.x = NU + ei[E + i];            // src row (entity half of g_all)
        rec.y = ety[i] - 1;                // weight row 0..14
    } else if (i < E + E2) {
        int e2 = i - E;
        d     = NE + e2i[e2];
        rec.x = e2i[E2 + e2];              // src row (node space)
        rec.y = 15 + e2ty[e2];             // weight row 15..30
    } else {
        int j = i - E - E2;
        d     = NE + NN + im_row[j];
        rec.x = im_col[j];                 // entity col
        rec.y = __float_as_int(im_val[j]); // raw im value
    }
    int pos = atomicAdd(g_cursor + d, 1);
    g_rec[pos] = rec;
}

// ---------------------------------------------------------------------------
// per-hop gathers: 8-lane group per destination row.
// Each lane: uint4 fp16 src (8 halves = 16B), 2x float4 fp32 weight, fp32 acc.
// ---------------------------------------------------------------------------
__device__ __forceinline__ float grp_sum8(float s) {
    #pragma unroll
    for (int o = 4; o; o >>= 1) s += __shfl_xor_sync(0xffffffffu, s, o);
    return s;
}

struct F8 { float4 a, b; };

__device__ __forceinline__ F8 h8_to_f8(uint4 h) {
    F8 r;
    float2 p0 = __half22float2(*(__half2*)&h.x);
    float2 p1 = __half22float2(*(__half2*)&h.y);
    float2 p2 = __half22float2(*(__half2*)&h.z);
    float2 p3 = __half22float2(*(__half2*)&h.w);
    r.a = make_float4(p0.x, p0.y, p1.x, p1.y);
    r.b = make_float4(p2.x, p2.y, p3.x, p3.y);
    return r;
}

__global__ void __launch_bounds__(256) gather_kernel(
    int flip, float* __restrict__ node_res, float* __restrict__ ent_out)
{
    const __half* prev = flip ? g_all1 : g_all0;
    __half*       next = flip ? g_all0 : g_all1;

    int gidx = (blockIdx.x * blockDim.x + threadIdx.x) >> 3;
    int lane = threadIdx.x & 7;
    if (gidx >= NE + NN) return;
    int start = g_rowptr[gidx], end = g_rowptr[gidx + 1];

    float4 accA = make_float4(0.f, 0.f, 0.f, 0.f);
    float4 accB = make_float4(0.f, 0.f, 0.f, 0.f);
    int e = start;
    for (; e + 1 < end; e += 2) {
        int2 r0 = __ldg(g_rec + e);
        int2 r1 = __ldg(g_rec + e + 1);
        uint4 h0 = *((const uint4*)(prev + (size_t)r0.x * C) + lane);
        uint4 h1 = *((const uint4*)(prev + (size_t)r1.x * C) + lane);
        const float4* w0p = (const float4*)(g_w + r0.y * C) + lane * 2;
        const float4* w1p = (const float4*)(g_w + r1.y * C) + lane * 2;
        float4 w0a = w0p[0], w0b = w0p[1];
        float4 w1a = w1p[0], w1b = w1p[1];
        F8 s0 = h8_to_f8(h0);
        F8 s1 = h8_to_f8(h1);
        accA.x += s0.a.x * w0a.x + s1.a.x * w1a.x;
        accA.y += s0.a.y * w0a.y + s1.a.y * w1a.y;
        accA.z += s0.a.z * w0a.z + s1.a.z * w1a.z;
        accA.w += s0.a.w * w0a.w + s1.a.w * w1a.w;
        accB.x += s0.b.x * w0b.x + s1.b.x * w1b.x;
        accB.y += s0.b.y * w0b.y + s1.b.y * w1b.y;
        accB.z += s0.b.z * w0b.z + s1.b.z * w1b.z;
        accB.w += s0.b.w * w0b.w + s1.b.w * w1b.w;
    }
    if (e < end) {
        int2 r0 = __ldg(g_rec + e);
        uint4 h0 = *((const uint4*)(prev + (size_t)r0.x * C) + lane);
        const float4* w0p = (const float4*)(g_w + r0.y * C) + lane * 2;
        float4 w0a = w0p[0], w0b = w0p[1];
        F8 s0 = h8_to_f8(h0);
        accA.x += s0.a.x * w0a.x; accA.y += s0.a.y * w0a.y;
        accA.z += s0.a.z * w0a.z; accA.w += s0.a.w * w0a.w;
        accB.x += s0.b.x * w0b.x; accB.y += s0.b.y * w0b.y;
        accB.z += s0.b.z * w0b.z; accB.w += s0.b.w * w0b.w;
    }

    float ss = grp_sum8(accA.x * accA.x + accA.y * accA.y + accA.z * accA.z + accA.w * accA.w
                      + accB.x * accB.x + accB.y * accB.y + accB.z * accB.z + accB.w * accB.w);
    float n  = sqrtf(ss);
    float inv = 1.0f / fmaxf(n, 1e-12f);
    float4 oa = make_float4(accA.x * inv, accA.y * inv, accA.z * inv, accA.w * inv);
    float4 ob = make_float4(accB.x * inv, accB.y * inv, accB.z * inv, accB.w * inv);
    uint4 oh;
    *(__half2*)&oh.x = __floats2half2_rn(oa.x, oa.y);
    *(__half2*)&oh.y = __floats2half2_rn(oa.z, oa.w);
    *(__half2*)&oh.z = __floats2half2_rn(ob.x, ob.y);
    *(__half2*)&oh.w = __floats2half2_rn(ob.z, ob.w);

    if (gidx < NE) {
        *((uint4*)(next + (size_t)(NU + gidx) * C) + lane) = oh;
        if (lane == 0) g_f[gidx] = n / fmaxf((float)(end - start), 1.0f);
        if (ent_out) {
            float4* op = (float4*)(ent_out + (size_t)gidx * C) + lane * 2;
            op[0] = oa; op[1] = ob;
        }
    } else {
        int r = gidx - NE;
        if (r < NU) *((uint4*)(next + (size_t)r * C) + lane) = oh;
        float4* rp = (float4*)(node_res + (size_t)r * C) + lane * 2;
        float4 a0 = rp[0], a1 = rp[1];
        a0.x += oa.x; a0.y += oa.y; a0.z += oa.z; a0.w += oa.w;
        a1.x += ob.x; a1.y += ob.y; a1.z += ob.z; a1.w += ob.w;
        rp[0] = a0; rp[1] = a1;
    }
}

__global__ void __launch_bounds__(256) im_gather_kernel(
    int flip, float* __restrict__ user_res)
{
    const __half* next = flip ? g_all0 : g_all1;   // buffer just written

    int gidx = (blockIdx.x * blockDim.x + threadIdx.x) >> 3;
    int lane = threadIdx.x & 7;
    if (gidx >= NU) return;
    int row = NE + NN + gidx;
    int start = g_rowptr[row], end = g_rowptr[row + 1];

    float4 accA = make_float4(0.f, 0.f, 0.f, 0.f);
    float4 accB = make_float4(0.f, 0.f, 0.f, 0.f);
    int e = start;
    for (; e + 1 < end; e += 2) {
        int2 r0 = __ldg(g_rec + e);
        int2 r1 = __ldg(g_rec + e + 1);
        float c0 = __int_as_float(r0.y) * __ldg(g_f + r0.x);
        float c1 = __int_as_float(r1.y) * __ldg(g_f + r1.x);
        uint4 h0 = *((const uint4*)(next + (size_t)(NU + r0.x) * C) + lane);
        uint4 h1 = *((const uint4*)(next + (size_t)(NU + r1.x) * C) + lane);
        F8 s0 = h8_to_f8(h0);
        F8 s1 = h8_to_f8(h1);
        accA.x += s0.a.x * c0 + s1.a.x * c1;
        accA.y += s0.a.y * c0 + s1.a.y * c1;
        accA.z += s0.a.z * c0 + s1.a.z * c1;
        accA.w += s0.a.w * c0 + s1.a.w * c1;
        accB.x += s0.b.x * c0 + s1.b.x * c1;
        accB.y += s0.b.y * c0 + s1.b.y * c1;
        accB.z += s0.b.z * c0 + s1.b.z * c1;
        accB.w += s0.b.w * c0 + s1.b.w * c1;
    }
    if (e < end) {
        int2 r0 = __ldg(g_rec + e);
        float c0 = __int_as_float(r0.y) * __ldg(g_f + r0.x);
        uint4 h0 = *((const uint4*)(next + (size_t)(NU + r0.x) * C) + lane);
        F8 s0 = h8_to_f8(h0);
        accA.x += s0.a.x * c0; accA.y += s0.a.y * c0;
        accA.z += s0.a.z * c0; accA.w += s0.a.w * c0;
        accB.x += s0.b.x * c0; accB.y += s0.b.y * c0;
        accB.z += s0.b.z * c0; accB.w += s0.b.w * c0;
    }

    float ss = grp_sum8(accA.x * accA.x + accA.y * accA.y + accA.z * accA.z + accA.w * accA.w
                      + accB.x * accB.x + accB.y * accB.y + accB.z * accB.z + accB.w * accB.w);
    float inv = 1.0f / fmaxf(sqrtf(ss), 1e-12f);
    float4* rp = (float4*)(user_res + (size_t)gidx * C) + lane * 2;
    float4 a0 = rp[0], a1 = rp[1];
    a0.x += accA.x * inv; a0.y += accA.y * inv;
    a0.z += accA.z * inv; a0.w += accA.w * inv;
    a1.x += accB.x * inv; a1.y += accB.y * inv;
    a1.z += accB.z * inv; a1.w += accB.w * inv;
    rp[0] = a0; rp[1] = a1;
}

// ---------------------------------------------------------------------------
extern "C" void kernel_launch(void* const* d_in, const int* in_sizes, int n_in,
                              void* d_out, int out_size) {
    const float* user_emb     = (const float*)d_in[0];
    const float* entity_emb   = (const float*)d_in[1];
    const float* weight       = (const float*)d_in[2];
    const float* extra_weight = (const float*)d_in[3];
    const float* im_val       = (const float*)d_in[4];
    const int*   edge_index   = (const int*)d_in[5];
    const int*   edge_type    = (const int*)d_in[6];
    const int*   extra_eidx   = (const int*)d_in[7];
    const int*   extra_etype  = (const int*)d_in[8];
    const int*   im_row       = (const int*)d_in[9];
    const int*   im_col       = (const int*)d_in[10];

    const int E   = in_sizes[6];
    const int E2  = in_sizes[8];
    const int NNZ = in_sizes[4];
    const int total_rec = E + E2 + NNZ;

    float* out      = (float*)d_out;
    float* user_res = out;                      // [NU, C]
    float* ent_out  = out + (size_t)NU * C;     // [NE, C]
    float* node_res = out + (size_t)NN * C;     // [NN, C]

    init_kernel<<<2048, 256>>>(user_emb, entity_emb, weight, extra_weight, out);
    hist_kernel<<<(total_rec + 255) / 256, 256>>>(edge_index, extra_eidx, im_row, E, E2, NNZ);
    scan1_kernel<<<NB, 256>>>();
    scan2_kernel<<<1, 512>>>();
    scan3_kernel<<<(NT + 255) / 256, 256>>>(total_rec);
    fill_kernel<<<(total_rec + 255) / 256, 256>>>(edge_index, edge_type,
                                                  extra_eidx, extra_etype,
                                                  im_row, im_col, im_val, E, E2, NNZ);

    const int gather_blocks = ((NE + NN) * 8 + 255) / 256;
    const int im_blocks     = (NU * 8 + 255) / 256;

    for (int hop = 0; hop < N_HOPS; hop++) {
        int flip = hop & 1;
        gather_kernel<<<gather_blocks, 256>>>(flip, node_res,
                                              hop == N_HOPS - 1 ? ent_out : nullptr);
        im_gather_kernel<<<im_blocks, 256>>>(flip, user_res);
    }
}

// round 9
// speedup vs baseline: 1.4516x; 1.1722x over previous
#include <cuda_runtime.h>
#include <cuda_fp16.h>

#define NU 100000
#define NE 100000
#define NN 200000
#define C  64
#define N_HOPS 3
#define NT (NE + NN + NU)            // combined destination space
#define MAXREC 4000000               // E + E2 + NNZ
#define SCAN_BLK 1024
#define NB ((NT + SCAN_BLK - 1) / SCAN_BLK)

// -------- persistent scratch (static device globals) --------
__device__ __align__(16) __half g_all0[(size_t)NN * C];  // ping (fp16)
__device__ __align__(16) __half g_all1[(size_t)NN * C];  // pong (fp16)
__device__ __align__(16) __half g_wh[32 * C];            // combined weight tables (fp16)
__device__ __align__(16) float  g_f[NE];                 // per-hop ||sum||/cnt
__device__ int   g_cnt[NT];
__device__ int   g_rowptr[NT + 1];
__device__ int   g_cursor[NT];
__device__ int   g_blocksums[NB];
__device__ int   g_reci[MAXREC];                         // packed edge rec / im col
__device__ float g_recv[1000000];                        // im values (CSR tail)

// ---------------------------------------------------------------------------
// init: g_all0 = fp16([user_emb ; entity_emb]); zero g_cnt; stage fp16 weights
// (output residuals are initialized by the hop-0 kernels, not here)
// ---------------------------------------------------------------------------
__global__ void init_kernel(const float* __restrict__ user_emb,
                            const float* __restrict__ entity_emb,
                            const float* __restrict__ w,
                            const float* __restrict__ w2) {
    const size_t nn4   = (size_t)NN * C / 4;
    const size_t nu4   = (size_t)NU * C / 4;
    const size_t cnt4  = NT / 4;
    const size_t total = nn4 + cnt4 + 31 * C;
    uint2*        all2 = (uint2*)g_all0;            // 4 halves per uint2
    const float4* ue4  = (const float4*)user_emb;
    const float4* ee4  = (const float4*)entity_emb;
    for (size_t i = (size_t)blockIdx.x * blockDim.x + threadIdx.x;
         i < total; i += (size_t)gridDim.x * blockDim.x) {
        if (i < nn4) {
            float4 v = (i < nu4) ? ue4[i] : ee4[i - nu4];
            uint2 h;
            *(__half2*)&h.x = __floats2half2_rn(v.x, v.y);
            *(__half2*)&h.y = __floats2half2_rn(v.z, v.w);
            all2[i] = h;
        } else if (i < nn4 + cnt4) {
            ((int4*)g_cnt)[i - nn4] = make_int4(0, 0, 0, 0);
        } else {
            size_t j = i - nn4 - cnt4;
            float x = (j < 15 * C) ? w[j] : w2[j - 15 * C];
            g_wh[j] = __float2half_rn(x);
        }
    }
}

// ---------------------------------------------------------------------------
// CSR build (one-time)
// dest space: [0,NE): entity edges | [NE,NE+NN): node edges | [NE+NN,NT): im
// ---------------------------------------------------------------------------
__global__ void hist_kernel(const int* __restrict__ ei,
                            const int* __restrict__ e2i,
                            const int* __restrict__ im_row,
                            int E, int E2, int NNZ) {
    int i = blockIdx.x * blockDim.x + threadIdx.x;
    int total = E + E2 + NNZ;
    if (i >= total) return;
    int d;
    if (i < E)           d = ei[i];
    else if (i < E + E2) d = NE + e2i[i - E];
    else                 d = NE + NN + im_row[i - E - E2];
    atomicAdd(g_cnt + d, 1);
}

__global__ void scan1_kernel() {
    __shared__ int s[256];
    int tid  = threadIdx.x;
    int base = blockIdx.x * SCAN_BLK + tid * 4;
    int v[4], t = 0;
    #pragma unroll
    for (int k = 0; k < 4; k++) {
        v[k] = (base + k < NT) ? g_cnt[base + k] : 0;
        t += v[k];
    }
    s[tid] = t;
    __syncthreads();
    #pragma unroll
    for (int off = 1; off < 256; off <<= 1) {
        int x = (tid >= off) ? s[tid - off] : 0;
        __syncthreads();
        s[tid] += x;
        __syncthreads();
    }
    int excl = s[tid] - t;
    if (tid == 255) g_blocksums[blockIdx.x] = s[255];
    int run = excl;
    #pragma unroll
    for (int k = 0; k < 4; k++) {
        if (base + k < NT) g_rowptr[base + k] = run;
        run += v[k];
    }
}

__global__ void scan2_kernel() {
    __shared__ int s[512];
    int tid = threadIdx.x;
    int v = (tid < NB) ? g_blocksums[tid] : 0;
    s[tid] = v;
    __syncthreads();
    #pragma unroll
    for (int off = 1; off < 512; off <<= 1) {
        int x = (tid >= off) ? s[tid - off] : 0;
        __syncthreads();
        s[tid] += x;
        __syncthreads();
    }
    if (tid < NB) g_blocksums[tid] = s[tid] - v;   // exclusive
}

__global__ void scan3_kernel(int total_rec) {
    int i = blockIdx.x * blockDim.x + threadIdx.x;
    if (i < NT) {
        int v = g_rowptr[i] + g_blocksums[i / SCAN_BLK];
        g_rowptr[i] = v;
        g_cursor[i] = v;
    }
    if (i == 0) g_rowptr[NT] = total_rec;
}

// edge recs pack (src_row*32 + weight_row) into one int; im recs = col + value
__global__ void fill_kernel(const int* __restrict__ ei,  const int* __restrict__ ety,
                            const int* __restrict__ e2i, const int* __restrict__ e2ty,
                            const int* __restrict__ im_row, const int* __restrict__ im_col,
                            const float* __restrict__ im_val,
                            int E, int E2, int NNZ) {
    int i = blockIdx.x * blockDim.x + threadIdx.x;
    int total = E + E2 + NNZ;
    if (i >= total) return;
    int EE2 = E + E2;
    int d, ival;
    float fval = 0.f;
    bool is_im = false;
    if (i < E) {
        d    = ei[i];
        ival = (NU + ei[E + i]) * 32 + (ety[i] - 1);
    } else if (i < EE2) {
        int e2 = i - E;
        d    = NE + e2i[e2];
        ival = e2i[E2 + e2] * 32 + (15 + e2ty[e2]);
    } else {
        int j = i - EE2;
        d     = NE + NN + im_row[j];
        ival  = im_col[j];
        fval  = im_val[j];
        is_im = true;
    }
    int pos = atomicAdd(g_cursor + d, 1);
    g_reci[pos] = ival;
    if (is_im) g_recv[pos - EE2] = fval;   // im recs occupy the CSR tail
}

// ---------------------------------------------------------------------------
// per-hop gathers: 8-lane group per destination row.
// fp16 src + fp16 weight (uint4 = 8 halves), fp32 accumulation.
// ---------------------------------------------------------------------------
__device__ __forceinline__ float grp_sum8(float s) {
    #pragma unroll
    for (int o = 4; o; o >>= 1) s += __shfl_xor_sync(0xffffffffu, s, o);
    return s;
}

struct F8 { float4 a, b; };

__device__ __forceinline__ F8 h8_to_f8(uint4 h) {
    F8 r;
    float2 p0 = __half22float2(*(__half2*)&h.x);
    float2 p1 = __half22float2(*(__half2*)&h.y);
    float2 p2 = __half22float2(*(__half2*)&h.z);
    float2 p3 = __half22float2(*(__half2*)&h.w);
    r.a = make_float4(p0.x, p0.y, p1.x, p1.y);
    r.b = make_float4(p2.x, p2.y, p3.x, p3.y);
    return r;
}

__global__ void __launch_bounds__(256) gather_kernel(
    int flip, int hop0,
    const float* __restrict__ user_emb, const float* __restrict__ entity_emb,
    float* __restrict__ node_res, float* __restrict__ ent_out)
{
    const __half* prev = flip ? g_all1 : g_all0;
    __half*       next = flip ? g_all0 : g_all1;

    int gidx = (blockIdx.x * blockDim.x + threadIdx.x) >> 3;
    int lane = threadIdx.x & 7;
    if (gidx >= NE + NN) return;
    int start = g_rowptr[gidx], end = g_rowptr[gidx + 1];

    float4 accA = make_float4(0.f, 0.f, 0.f, 0.f);
    float4 accB = make_float4(0.f, 0.f, 0.f, 0.f);
    int e = start;
    for (; e + 1 < end; e += 2) {
        int r0 = __ldg(g_reci + e);
        int r1 = __ldg(g_reci + e + 1);
        uint4 h0 = *((const uint4*)(prev + (size_t)(r0 >> 5) * C) + lane);
        uint4 h1 = *((const uint4*)(prev + (size_t)(r1 >> 5) * C) + lane);
        uint4 wh0 = *((const uint4*)(g_wh + (r0 & 31) * C) + lane);
        uint4 wh1 = *((const uint4*)(g_wh + (r1 & 31) * C) + lane);
        F8 s0 = h8_to_f8(h0), s1 = h8_to_f8(h1);
        F8 w0 = h8_to_f8(wh0), w1 = h8_to_f8(wh1);
        accA.x += s0.a.x * w0.a.x + s1.a.x * w1.a.x;
        accA.y += s0.a.y * w0.a.y + s1.a.y * w1.a.y;
        accA.z += s0.a.z * w0.a.z + s1.a.z * w1.a.z;
        accA.w += s0.a.w * w0.a.w + s1.a.w * w1.a.w;
        accB.x += s0.b.x * w0.b.x + s1.b.x * w1.b.x;
        accB.y += s0.b.y * w0.b.y + s1.b.y * w1.b.y;
        accB.z += s0.b.z * w0.b.z + s1.b.z * w1.b.z;
        accB.w += s0.b.w * w0.b.w + s1.b.w * w1.b.w;
    }
    if (e < end) {
        int r0 = __ldg(g_reci + e);
        uint4 h0 = *((const uint4*)(prev + (size_t)(r0 >> 5) * C) + lane);
        uint4 wh0 = *((const uint4*)(g_wh + (r0 & 31) * C) + lane);
        F8 s0 = h8_to_f8(h0);
        F8 w0 = h8_to_f8(wh0);
        accA.x += s0.a.x * w0.a.x; accA.y += s0.a.y * w0.a.y;
        accA.z += s0.a.z * w0.a.z; accA.w += s0.a.w * w0.a.w;
        accB.x += s0.b.x * w0.b.x; accB.y += s0.b.y * w0.b.y;
        accB.z += s0.b.z * w0.b.z; accB.w += s0.b.w * w0.b.w;
    }

    float ss = grp_sum8(accA.x * accA.x + accA.y * accA.y + accA.z * accA.z + accA.w * accA.w
                      + accB.x * accB.x + accB.y * accB.y + accB.z * accB.z + accB.w * accB.w);
    float n  = sqrtf(ss);
    float inv = 1.0f / fmaxf(n, 1e-12f);
    float4 oa = make_float4(accA.x * inv, accA.y * inv, accA.z * inv, accA.w * inv);
    float4 ob = make_float4(accB.x * inv, accB.y * inv, accB.z * inv, accB.w * inv);
    uint4 oh;
    *(__half2*)&oh.x = __floats2half2_rn(oa.x, oa.y);
    *(__half2*)&oh.y = __floats2half2_rn(oa.z, oa.w);
    *(__half2*)&oh.z = __floats2half2_rn(ob.x, ob.y);
    *(__half2*)&oh.w = __floats2half2_rn(ob.z, ob.w);

    if (gidx < NE) {
        *((uint4*)(next + (size_t)(NU + gidx) * C) + lane) = oh;
        if (lane == 0) g_f[gidx] = n / fmaxf((float)(end - start), 1.0f);
        if (ent_out) {
            float4* op = (float4*)(ent_out + (size_t)gidx * C) + lane * 2;
            op[0] = oa; op[1] = ob;
        }
    } else {
        int r = gidx - NE;
        if (r < NU) *((uint4*)(next + (size_t)r * C) + lane) = oh;
        float4* rp = (float4*)(node_res + (size_t)r * C) + lane * 2;
        float4 a0, a1;
        if (hop0) {
            // residual starts from the original embedding (read from inputs)
            const float4* ip = (r < NU)
                ? (const float4*)(user_emb + (size_t)r * C) + lane * 2
                : (const float4*)(entity_emb + (size_t)(r - NU) * C) + lane * 2;
            a0 = ip[0]; a1 = ip[1];
        } else {
            a0 = rp[0]; a1 = rp[1];
        }
        a0.x += oa.x; a0.y += oa.y; a0.z += oa.z; a0.w += oa.w;
        a1.x += ob.x; a1.y += ob.y; a1.z += ob.z; a1.w += ob.w;
        rp[0] = a0; rp[1] = a1;
    }
}

__global__ void __launch_bounds__(256) im_gather_kernel(
    int flip, int hop0, int EE2,
    const float* __restrict__ user_emb, float* __restrict__ user_res)
{
    const __half* next = flip ? g_all0 : g_all1;   // buffer just written

    int gidx = (blockIdx.x * blockDim.x + threadIdx.x) >> 3;
    int lane = threadIdx.x & 7;
    if (gidx >= NU) return;
    int row = NE + NN + gidx;
    int start = g_rowptr[row], end = g_rowptr[row + 1];

    float4 accA = make_float4(0.f, 0.f, 0.f, 0.f);
    float4 accB = make_float4(0.f, 0.f, 0.f, 0.f);
    int e = start;
    for (; e + 1 < end; e += 2) {
        int c0i = __ldg(g_reci + e);
        int c1i = __ldg(g_reci + e + 1);
        float c0 = __ldg(g_recv + (e - EE2))     * __ldg(g_f + c0i);
        float c1 = __ldg(g_recv + (e + 1 - EE2)) * __ldg(g_f + c1i);
        uint4 h0 = *((const uint4*)(next + (size_t)(NU + c0i) * C) + lane);
        uint4 h1 = *((const uint4*)(next + (size_t)(NU + c1i) * C) + lane);
        F8 s0 = h8_to_f8(h0);
        F8 s1 = h8_to_f8(h1);
        accA.x += s0.a.x * c0 + s1.a.x * c1;
        accA.y += s0.a.y * c0 + s1.a.y * c1;
        accA.z += s0.a.z * c0 + s1.a.z * c1;
        accA.w += s0.a.w * c0 + s1.a.w * c1;
        accB.x += s0.b.x * c0 + s1.b.x * c1;
        accB.y += s0.b.y * c0 + s1.b.y * c1;
        accB.z += s0.b.z * c0 + s1.b.z * c1;
        accB.w += s0.b.w * c0 + s1.b.w * c1;
    }
    if (e < end) {
        int c0i = __ldg(g_reci + e);
        float c0 = __ldg(g_recv + (e - EE2)) * __ldg(g_f + c0i);
        uint4 h0 = *((const uint4*)(next + (size_t)(NU + c0i) * C) + lane);
        F8 s0 = h8_to_f8(h0);
        accA.x += s0.a.x * c0; accA.y += s0.a.y * c0;
        accA.z += s0.a.z * c0; accA.w += s0.a.w * c0;
        accB.x += s0.b.x * c0; accB.y += s0.b.y * c0;
        accB.z += s0.b.z * c0; accB.w += s0.b.w * c0;
    }

    float ss = grp_sum8(accA.x * accA.x + accA.y * accA.y + accA.z * accA.z + accA.w * accA.w
                      + accB.x * accB.x + accB.y * accB.y + accB.z * accB.z + accB.w * accB.w);
    float inv = 1.0f / fmaxf(sqrtf(ss), 1e-12f);
    float4* rp = (float4*)(user_res + (size_t)gidx * C) + lane * 2;
    float4 a0, a1;
    if (hop0) {
        const float4* ip = (const float4*)(user_emb + (size_t)gidx * C) + lane * 2;
        a0 = ip[0]; a1 = ip[1];
    } else {
        a0 = rp[0]; a1 = rp[1];
    }
    a0.x += accA.x * inv; a0.y += accA.y * inv;
    a0.z += accA.z * inv; a0.w += accA.w * inv;
    a1.x += accB.x * inv; a1.y += accB.y * inv;
    a1.z += accB.z * inv; a1.w += accB.w * inv;
    rp[0] = a0; rp[1] = a1;
}

// ---------------------------------------------------------------------------
extern "C" void kernel_launch(void* const* d_in, const int* in_sizes, int n_in,
                              void* d_out, int out_size) {
    const float* user_emb     = (const float*)d_in[0];
    const float* entity_emb   = (const float*)d_in[1];
    const float* weight       = (const float*)d_in[2];
    const float* extra_weight = (const float*)d_in[3];
    const float* im_val       = (const float*)d_in[4];
    const int*   edge_index   = (const int*)d_in[5];
    const int*   edge_type    = (const int*)d_in[6];
    const int*   extra_eidx   = (const int*)d_in[7];
    const int*   extra_etype  = (const int*)d_in[8];
    const int*   im_row       = (const int*)d_in[9];
    const int*   im_col       = (const int*)d_in[10];

    const int E   = in_sizes[6];
    const int E2  = in_sizes[8];
    const int NNZ = in_sizes[4];
    const int total_rec = E + E2 + NNZ;
    const int EE2 = E + E2;

    float* out      = (float*)d_out;
    float* user_res = out;                      // [NU, C]
    float* ent_out  = out + (size_t)NU * C;     // [NE, C]
    float* node_res = out + (size_t)NN * C;     // [NN, C]

    init_kernel<<<2048, 256>>>(user_emb, entity_emb, weight, extra_weight);
    hist_kernel<<<(total_rec + 255) / 256, 256>>>(edge_index, extra_eidx, im_row, E, E2, NNZ);
    scan1_kernel<<<NB, 256>>>();
    scan2_kernel<<<1, 512>>>();
    scan3_kernel<<<(NT + 255) / 256, 256>>>(total_rec);
    fill_kernel<<<(total_rec + 255) / 256, 256>>>(edge_index, edge_type,
                                                  extra_eidx, extra_etype,
                                                  im_row, im_col, im_val, E, E2, NNZ);

    const int gather_blocks = ((NE + NN) * 8 + 255) / 256;
    const int im_blocks     = (NU * 8 + 255) / 256;

    for (int hop = 0; hop < N_HOPS; hop++) {
        int flip = hop & 1;
        int hop0 = (hop == 0) ? 1 : 0;
        gather_kernel<<<gather_blocks, 256>>>(flip, hop0, user_emb, entity_emb,
                                              node_res,
                                              hop == N_HOPS - 1 ? ent_out : nullptr);
        im_gather_kernel<<<im_blocks, 256>>>(flip, hop0, EE2, user_emb, user_res);
    }
}

// round 10
// speedup vs baseline: 1.4775x; 1.0178x over previous
#include <cuda_runtime.h>
#include <cuda_fp16.h>

#define NU 100000
#define NE 100000
#define NN 200000
#define C  64
#define N_HOPS 3
#define NT (NE + NN + NU)            // combined destination space
#define MAXREC 4000000               // E + E2 + NNZ
#define SCAN_BLK 1024
#define NB ((NT + SCAN_BLK - 1) / SCAN_BLK)

// -------- persistent scratch (static device globals) --------
__device__ __align__(16) __half g_all0[(size_t)NN * C];  // ping (fp16)
__device__ __align__(16) __half g_all1[(size_t)NN * C];  // pong (fp16)
__device__ __align__(16) __half g_wh[32 * C];            // combined weight tables (fp16)
__device__ __align__(16) float  g_f[2 * NE];             // ||sum||/cnt, double-buffered by hop parity
__device__ int   g_cnt[NT];
__device__ int   g_rowptr[NT + 1];
__device__ int   g_cursor[NT];
__device__ int   g_blocksums[NB];
__device__ int   g_reci[MAXREC];                         // packed edge rec / im col
__device__ float g_recv[1000000];                        // im values (CSR tail)

// buffer written by gather hop h (h = -1 means the initial embedding buffer)
__device__ __forceinline__ const __half* buf_of(int h) {
    return (h & 1) ? g_all0 : g_all1;       // -1->all0, 0->all1, 1->all0, 2->all1
}
__device__ __forceinline__ __half* buf_of_mut(int h) {
    return (h & 1) ? g_all0 : g_all1;
}

// ---------------------------------------------------------------------------
// init: g_all0 = fp16([user_emb ; entity_emb]); zero g_cnt; stage fp16 weights
// ---------------------------------------------------------------------------
__global__ void init_kernel(const float* __restrict__ user_emb,
                            const float* __restrict__ entity_emb,
                            const float* __restrict__ w,
                            const float* __restrict__ w2) {
    const size_t nn4   = (size_t)NN * C / 4;
    const size_t nu4   = (size_t)NU * C / 4;
    const size_t cnt4  = NT / 4;
    const size_t total = nn4 + cnt4 + 31 * C;
    uint2*        all2 = (uint2*)g_all0;            // 4 halves per uint2
    const float4* ue4  = (const float4*)user_emb;
    const float4* ee4  = (const float4*)entity_emb;
    for (size_t i = (size_t)blockIdx.x * blockDim.x + threadIdx.x;
         i < total; i += (size_t)gridDim.x * blockDim.x) {
        if (i < nn4) {
            float4 v = (i < nu4) ? ue4[i] : ee4[i - nu4];
            uint2 h;
            *(__half2*)&h.x = __floats2half2_rn(v.x, v.y);
            *(__half2*)&h.y = __floats2half2_rn(v.z, v.w);
            all2[i] = h;
        } else if (i < nn4 + cnt4) {
            ((int4*)g_cnt)[i - nn4] = make_int4(0, 0, 0, 0);
        } else {
            size_t j = i - nn4 - cnt4;
            float x = (j < 15 * C) ? w[j] : w2[j - 15 * C];
            g_wh[j] = __float2half_rn(x);
        }
    }
}

// ---------------------------------------------------------------------------
// CSR build (one-time)
// dest space: [0,NE): entity edges | [NE,NE+NN): node edges | [NE+NN,NT): im
// ---------------------------------------------------------------------------
__global__ void hist_kernel(const int* __restrict__ ei,
                            const int* __restrict__ e2i,
                            const int* __restrict__ im_row,
                            int E, int E2, int NNZ) {
    int i = blockIdx.x * blockDim.x + threadIdx.x;
    int total = E + E2 + NNZ;
    if (i >= total) return;
    int d;
    if (i < E)           d = ei[i];
    else if (i < E + E2) d = NE + e2i[i - E];
    else                 d = NE + NN + im_row[i - E - E2];
    atomicAdd(g_cnt + d, 1);
}

__global__ void scan1_kernel() {
    __shared__ int s[256];
    int tid  = threadIdx.x;
    int base = blockIdx.x * SCAN_BLK + tid * 4;
    int v[4], t = 0;
    #pragma unroll
    for (int k = 0; k < 4; k++) {
        v[k] = (base + k < NT) ? g_cnt[base + k] : 0;
        t += v[k];
    }
    s[tid] = t;
    __syncthreads();
    #pragma unroll
    for (int off = 1; off < 256; off <<= 1) {
        int x = (tid >= off) ? s[tid - off] : 0;
        __syncthreads();
        s[tid] += x;
        __syncthreads();
    }
    int excl = s[tid] - t;
    if (tid == 255) g_blocksums[blockIdx.x] = s[255];
    int run = excl;
    #pragma unroll
    for (int k = 0; k < 4; k++) {
        if (base + k < NT) g_rowptr[base + k] = run;
        run += v[k];
    }
}

__global__ void scan2_kernel() {
    __shared__ int s[512];
    int tid = threadIdx.x;
    int v = (tid < NB) ? g_blocksums[tid] : 0;
    s[tid] = v;
    __syncthreads();
    #pragma unroll
    for (int off = 1; off < 512; off <<= 1) {
        int x = (tid >= off) ? s[tid - off] : 0;
        __syncthreads();
        s[tid] += x;
        __syncthreads();
    }
    if (tid < NB) g_blocksums[tid] = s[tid] - v;   // exclusive
}

__global__ void scan3_kernel(int total_rec) {
    int i = blockIdx.x * blockDim.x + threadIdx.x;
    if (i < NT) {
        int v = g_rowptr[i] + g_blocksums[i / SCAN_BLK];
        g_rowptr[i] = v;
        g_cursor[i] = v;
    }
    if (i == 0) g_rowptr[NT] = total_rec;
}

// edge recs pack (src_row*32 + weight_row) into one int; im recs = col + value
__global__ void fill_kernel(const int* __restrict__ ei,  const int* __restrict__ ety,
                            const int* __restrict__ e2i, const int* __restrict__ e2ty,
                            const int* __restrict__ im_row, const int* __restrict__ im_col,
                            const float* __restrict__ im_val,
                            int E, int E2, int NNZ) {
    int i = blockIdx.x * blockDim.x + threadIdx.x;
    int total = E + E2 + NNZ;
    if (i >= total) return;
    int EE2 = E + E2;
    int d, ival;
    float fval = 0.f;
    bool is_im = false;
    if (i < E) {
        d    = ei[i];
        ival = (NU + ei[E + i]) * 32 + (ety[i] - 1);
    } else if (i < EE2) {
        int e2 = i - E;
        d    = NE + e2i[e2];
        ival = e2i[E2 + e2] * 32 + (15 + e2ty[e2]);
    } else {
        int j = i - EE2;
        d     = NE + NN + im_row[j];
        ival  = im_col[j];
        fval  = im_val[j];
        is_im = true;
    }
    int pos = atomicAdd(g_cursor + d, 1);
    g_reci[pos] = ival;
    if (is_im) g_recv[pos - EE2] = fval;   // im recs occupy the CSR tail
}

// ---------------------------------------------------------------------------
// fused per-hop kernel: 8-lane group per destination row.
//   gidx in [0, NE+NN)      : gather for hop_g  (if do_g)
//   gidx in [NE+NN, NT)     : im     for hop_m  (if do_m)
// gather hop g : reads buf(g-1), writes buf(g), writes g_f[(g&1)*NE + row]
// im     hop m : reads buf(m), reads g_f[(m&1)*NE + col]
// ---------------------------------------------------------------------------
__device__ __forceinline__ float grp_sum8(float s) {
    #pragma unroll
    for (int o = 4; o; o >>= 1) s += __shfl_xor_sync(0xffffffffu, s, o);
    return s;
}

struct F8 { float4 a, b; };

__device__ __forceinline__ F8 h8_to_f8(uint4 h) {
    F8 r;
    float2 p0 = __half22float2(*(__half2*)&h.x);
    float2 p1 = __half22float2(*(__half2*)&h.y);
    float2 p2 = __half22float2(*(__half2*)&h.z);
    float2 p3 = __half22float2(*(__half2*)&h.w);
    r.a = make_float4(p0.x, p0.y, p1.x, p1.y);
    r.b = make_float4(p2.x, p2.y, p3.x, p3.y);
    return r;
}

__global__ void __launch_bounds__(256) fused_kernel(
    int hop_g, int do_g, int hop_m, int do_m, int base, int EE2,
    const float* __restrict__ user_emb, const float* __restrict__ entity_emb,
    float* __restrict__ node_res, float* __restrict__ ent_out,
    float* __restrict__ user_res)
{
    int gidx = base + ((blockIdx.x * blockDim.x + threadIdx.x) >> 3);
    int lane = threadIdx.x & 7;

    if (gidx < NE + NN) {
        // ---------------- gather path (hop_g) ----------------
        if (!do_g) return;
        const __half* prev = buf_of(hop_g - 1);
        __half*       next = buf_of_mut(hop_g);
        float*        fdst = g_f + (hop_g & 1) * NE;
        int hop0 = (hop_g == 0);

        int start = g_rowptr[gidx], end = g_rowptr[gidx + 1];
        float4 accA = make_float4(0.f, 0.f, 0.f, 0.f);
        float4 accB = make_float4(0.f, 0.f, 0.f, 0.f);
        int e = start;
        for (; e + 1 < end; e += 2) {
            int r0 = __ldg(g_reci + e);
            int r1 = __ldg(g_reci + e + 1);
            uint4 h0 = *((const uint4*)(prev + (size_t)(r0 >> 5) * C) + lane);
            uint4 h1 = *((const uint4*)(prev + (size_t)(r1 >> 5) * C) + lane);
            uint4 wh0 = *((const uint4*)(g_wh + (r0 & 31) * C) + lane);
            uint4 wh1 = *((const uint4*)(g_wh + (r1 & 31) * C) + lane);
            F8 s0 = h8_to_f8(h0), s1 = h8_to_f8(h1);
            F8 w0 = h8_to_f8(wh0), w1 = h8_to_f8(wh1);
            accA.x += s0.a.x * w0.a.x + s1.a.x * w1.a.x;
            accA.y += s0.a.y * w0.a.y + s1.a.y * w1.a.y;
            accA.z += s0.a.z * w0.a.z + s1.a.z * w1.a.z;
            accA.w += s0.a.w * w0.a.w + s1.a.w * w1.a.w;
            accB.x += s0.b.x * w0.b.x + s1.b.x * w1.b.x;
            accB.y += s0.b.y * w0.b.y + s1.b.y * w1.b.y;
            accB.z += s0.b.z * w0.b.z + s1.b.z * w1.b.z;
            accB.w += s0.b.w * w0.b.w + s1.b.w * w1.b.w;
        }
        if (e < end) {
            int r0 = __ldg(g_reci + e);
            uint4 h0 = *((const uint4*)(prev + (size_t)(r0 >> 5) * C) + lane);
            uint4 wh0 = *((const uint4*)(g_wh + (r0 & 31) * C) + lane);
            F8 s0 = h8_to_f8(h0);
            F8 w0 = h8_to_f8(wh0);
            accA.x += s0.a.x * w0.a.x; accA.y += s0.a.y * w0.a.y;
            accA.z += s0.a.z * w0.a.z; accA.w += s0.a.w * w0.a.w;
            accB.x += s0.b.x * w0.b.x; accB.y += s0.b.y * w0.b.y;
            accB.z += s0.b.z * w0.b.z; accB.w += s0.b.w * w0.b.w;
        }

        float ss = grp_sum8(accA.x * accA.x + accA.y * accA.y + accA.z * accA.z + accA.w * accA.w
                          + accB.x * accB.x + accB.y * accB.y + accB.z * accB.z + accB.w * accB.w);
        float n  = sqrtf(ss);
        float inv = 1.0f / fmaxf(n, 1e-12f);
        float4 oa = make_float4(accA.x * inv, accA.y * inv, accA.z * inv, accA.w * inv);
        float4 ob = make_float4(accB.x * inv, accB.y * inv, accB.z * inv, accB.w * inv);
        uint4 oh;
        *(__half2*)&oh.x = __floats2half2_rn(oa.x, oa.y);
        *(__half2*)&oh.y = __floats2half2_rn(oa.z, oa.w);
        *(__half2*)&oh.z = __floats2half2_rn(ob.x, ob.y);
        *(__half2*)&oh.w = __floats2half2_rn(ob.z, ob.w);

        if (gidx < NE) {
            *((uint4*)(next + (size_t)(NU + gidx) * C) + lane) = oh;
            if (lane == 0) fdst[gidx] = n / fmaxf((float)(end - start), 1.0f);
            if (hop_g == N_HOPS - 1) {
                float4* op = (float4*)(ent_out + (size_t)gidx * C) + lane * 2;
                op[0] = oa; op[1] = ob;
            }
        } else {
            int r = gidx - NE;
            if (r < NU) *((uint4*)(next + (size_t)r * C) + lane) = oh;
            float4* rp = (float4*)(node_res + (size_t)r * C) + lane * 2;
            float4 a0, a1;
            if (hop0) {
                const float4* ip = (r < NU)
                    ? (const float4*)(user_emb + (size_t)r * C) + lane * 2
                    : (const float4*)(entity_emb + (size_t)(r - NU) * C) + lane * 2;
                a0 = ip[0]; a1 = ip[1];
            } else {
                a0 = rp[0]; a1 = rp[1];
            }
            a0.x += oa.x; a0.y += oa.y; a0.z += oa.z; a0.w += oa.w;
            a1.x += ob.x; a1.y += ob.y; a1.z += ob.z; a1.w += ob.w;
            rp[0] = a0; rp[1] = a1;
        }
    } else if (gidx < NT) {
        // ---------------- im path (hop_m) ----------------
        if (!do_m) return;
        const __half* src  = buf_of(hop_m);
        const float*  fsrc = g_f + (hop_m & 1) * NE;
        int hop0 = (hop_m == 0);
        int u = gidx - NE - NN;

        int start = g_rowptr[gidx], end = g_rowptr[gidx + 1];
        float4 accA = make_float4(0.f, 0.f, 0.f, 0.f);
        float4 accB = make_float4(0.f, 0.f, 0.f, 0.f);
        int e = start;
        for (; e + 1 < end; e += 2) {
            int c0i = __ldg(g_reci + e);
            int c1i = __ldg(g_reci + e + 1);
            float c0 = __ldg(g_recv + (e - EE2))     * __ldg(fsrc + c0i);
            float c1 = __ldg(g_recv + (e + 1 - EE2)) * __ldg(fsrc + c1i);
            uint4 h0 = *((const uint4*)(src + (size_t)(NU + c0i) * C) + lane);
            uint4 h1 = *((const uint4*)(src + (size_t)(NU + c1i) * C) + lane);
            F8 s0 = h8_to_f8(h0);
            F8 s1 = h8_to_f8(h1);
            accA.x += s0.a.x * c0 + s1.a.x * c1;
            accA.y += s0.a.y * c0 + s1.a.y * c1;
            accA.z += s0.a.z * c0 + s1.a.z * c1;
            accA.w += s0.a.w * c0 + s1.a.w * c1;
            accB.x += s0.b.x * c0 + s1.b.x * c1;
            accB.y += s0.b.y * c0 + s1.b.y * c1;
            accB.z += s0.b.z * c0 + s1.b.z * c1;
            accB.w += s0.b.w * c0 + s1.b.w * c1;
        }
        if (e < end) {
            int c0i = __ldg(g_reci + e);
            float c0 = __ldg(g_recv + (e - EE2)) * __ldg(fsrc + c0i);
            uint4 h0 = *((const uint4*)(src + (size_t)(NU + c0i) * C) + lane);
            F8 s0 = h8_to_f8(h0);
            accA.x += s0.a.x * c0; accA.y += s0.a.y * c0;
            accA.z += s0.a.z * c0; accA.w += s0.a.w * c0;
            accB.x += s0.b.x * c0; accB.y += s0.b.y * c0;
            accB.z += s0.b.z * c0; accB.w += s0.b.w * c0;
        }

        float ss = grp_sum8(accA.x * accA.x + accA.y * accA.y + accA.z * accA.z + accA.w * accA.w
                          + accB.x * accB.x + accB.y * accB.y + accB.z * accB.z + accB.w * accB.w);
        float inv = 1.0f / fmaxf(sqrtf(ss), 1e-12f);
        float4* rp = (float4*)(user_res + (size_t)u * C) + lane * 2;
        float4 a0, a1;
        if (hop0) {
            const float4* ip = (const float4*)(user_emb + (size_t)u * C) + lane * 2;
            a0 = ip[0]; a1 = ip[1];
        } else {
            a0 = rp[0]; a1 = rp[1];
        }
        a0.x += accA.x * inv; a0.y += accA.y * inv;
        a0.z += accA.z * inv; a0.w += accA.w * inv;
        a1.x += accB.x * inv; a1.y += accB.y * inv;
        a1.z += accB.z * inv; a1.w += accB.w * inv;
        rp[0] = a0; rp[1] = a1;
    }
}

// ---------------------------------------------------------------------------
extern "C" void kernel_launch(void* const* d_in, const int* in_sizes, int n_in,
                              void* d_out, int out_size) {
    const float* user_emb     = (const float*)d_in[0];
    const float* entity_emb   = (const float*)d_in[1];
    const float* weight       = (const float*)d_in[2];
    const float* extra_weight = (const float*)d_in[3];
    const float* im_val       = (const float*)d_in[4];
    const int*   edge_index   = (const int*)d_in[5];
    const int*   edge_type    = (const int*)d_in[6];
    const int*   extra_eidx   = (const int*)d_in[7];
    const int*   extra_etype  = (const int*)d_in[8];
    const int*   im_row       = (const int*)d_in[9];
    const int*   im_col       = (const int*)d_in[10];

    const int E   = in_sizes[6];
    const int E2  = in_sizes[8];
    const int NNZ = in_sizes[4];
    const int total_rec = E + E2 + NNZ;
    const int EE2 = E + E2;

    float* out      = (float*)d_out;
    float* user_res = out;                      // [NU, C]
    float* ent_out  = out + (size_t)NU * C;     // [NE, C]
    float* node_res = out + (size_t)NN * C;     // [NN, C]

    init_kernel<<<2048, 256>>>(user_emb, entity_emb, weight, extra_weight);
    hist_kernel<<<(total_rec + 255) / 256, 256>>>(edge_index, extra_eidx, im_row, E, E2, NNZ);
    scan1_kernel<<<NB, 256>>>();
    scan2_kernel<<<1, 512>>>();
    scan3_kernel<<<(NT + 255) / 256, 256>>>(total_rec);
    fill_kernel<<<(total_rec + 255) / 256, 256>>>(edge_index, edge_type,
                                                  extra_eidx, extra_etype,
                                                  im_row, im_col, im_val, E, E2, NNZ);

    const int g_blocks  = ((NE + NN) * 8 + 255) / 256;   // gather-only
    const int gm_blocks = (NT * 8 + 255) / 256;          // gather + im
    const int m_blocks  = (NU * 8 + 255) / 256;          // im-only

    // g0 ; [im0 || g1] ; [im1 || g2] ; im2
    fused_kernel<<<g_blocks, 256>>>(0, 1, 0, 0, 0, EE2,
                                    user_emb, entity_emb, node_res, ent_out, user_res);
    fused_kernel<<<gm_blocks, 256>>>(1, 1, 0, 1, 0, EE2,
                                     user_emb, entity_emb, node_res, ent_out, user_res);
    fused_kernel<<<gm_blocks, 256>>>(2, 1, 1, 1, 0, EE2,
                                     user_emb, entity_emb, node_res, ent_out, user_res);
    fused_kernel<<<m_blocks, 256>>>(0, 0, 2, 1, NE + NN, EE2,
                                    user_emb, entity_emb, node_res, ent_out, user_res);
}